// round 15
// baseline (speedup 1.0000x reference)
#include <cuda_runtime.h>

// SIR scan, (B,T,F) = (16384, 2048, 2) fp32, 2048 sequential steps per row.
// R6/R9/R11/R12 all pinned at 5.2 TB/s. Shared flaw: chunk c+3 was issued only
// AFTER consuming c (refill slot == consumed slot), serializing the fetch
// stream behind the compute. R13-R15: NBUF=5 ring, prefill 4, and issue chunk
// c+4 IMMEDIATELY after wait_group(3) lands chunk c -- refill slot (c+4)%5 is
// the slot freed in the previous iteration, so issue no longer waits on
// consume. 4 chunks (34 KB/warp) permanently in flight; one __syncwarp per
// chunk. R15: STATIC __shared__ (43520 B < 48 KB) instead of dynamic smem +
// cudaFuncSetAttribute, removing the only structural delta vs. kernels that
// benched successfully (two container failures on the dynamic-smem variant).

#define TT       2048
#define FF       2
#define CHUNK    32                    // timesteps per chunk
#define ROWV4    (CHUNK * FF / 4)      // 16 float4 per row-chunk (256 B)
#define NCH      (TT / CHUNK)          // 64 chunks
#define BDIM     32                    // 1 warp per block
#define WROWS    32                    // rows per block/warp
#define STR_V4   17                    // padded row stride in float4
#define WBUFV4   (WROWS * STR_V4)      // 544 float4 per buffer
#define NBUF     5                     // 5 x 8704 B = 43520 B static smem
#define ROW_STR4 (TT * FF / 4)         // 1024 float4 per global row

#define INV_POP 1e-6f

__device__ __forceinline__ void cp_async16(unsigned smem_addr, const float4* gmem_src) {
    asm volatile("cp.async.cg.shared.global [%0], [%1], 16;\n" :: "r"(smem_addr), "l"(gmem_src));
}
__device__ __forceinline__ void cp_commit() {
    asm volatile("cp.async.commit_group;\n" ::);
}

// 5-op SIR step; R recovered at the end via exact conservation.
__device__ __forceinline__ void sir_step(float& S, float& I,
                                         float beta, float gamma) {
    float bp = beta * INV_POP;           // off-chain (data only)
    float a  = bp * S;                   // chain
    float d  = a - gamma;                // chain
    float Sn = __fmaf_rn(-a, I, S);      // S - new_inf
    float In = __fmaf_rn( d, I, I);      // I + (a - gamma)*I
    S = Sn;
    I = In;
}

__global__ __launch_bounds__(BDIM, 4)
void sir_scan_kernel(const float* __restrict__ in,     // (B, T, F)
                     const float* __restrict__ init,   // (B, 3)
                     float* __restrict__ out,          // copies x (B, 3)
                     int B, int copies) {
    __shared__ float4 smem[NBUF * WBUFV4];             // 43520 B static

    const int lane = threadIdx.x;      // 0..31
    const int row0 = blockIdx.x * WROWS;
    const int b    = row0 + lane;

    const float4* gin = reinterpret_cast<const float4*>(in);

    float S = 0.f, I = 0.f, total = 0.f;
    if (b < B) {
        S = init[3 * b + 0];
        I = init[3 * b + 1];
        total = S + I + init[3 * b + 2];   // conserved quantity
    }

    // Staging map: slot s = k*32 + lane; 16 consecutive lanes cover one row's
    // 256 B chunk -> each warp cp.async = 2 rows x 2 lines = 4 wavefronts.
    const float4* gbase[ROWV4];
    unsigned      soff [ROWV4];
#pragma unroll
    for (int k = 0; k < ROWV4; k++) {
        int s   = k * WROWS + lane;
        int row = s >> 4;              // 0..31
        int off = s & 15;              // 0..15
        int gr  = row0 + row;
        if (gr >= B) gr = B - 1;
        gbase[k] = gin + (size_t)gr * ROW_STR4 + off;
        soff[k]  = (unsigned)((row * STR_V4 + off) * sizeof(float4));
    }
    const unsigned sbase    = (unsigned)__cvta_generic_to_shared(smem);
    const unsigned bufbytes = (unsigned)(WBUFV4 * sizeof(float4));

    // Prologue: fill 4 of the 5 buffers (chunks 0..3)
#pragma unroll
    for (int p = 0; p < NBUF - 1; p++) {
        unsigned sb = sbase + (unsigned)p * bufbytes;
#pragma unroll
        for (int k = 0; k < ROWV4; k++)
            cp_async16(sb + soff[k], gbase[k] + (size_t)p * ROWV4);
        cp_commit();
    }

    int slot  = 0;                     // slot of chunk c  (c mod 5)
    int islot = NBUF - 1;              // slot of chunk c+4 ((c+4) mod 5)
#pragma unroll 1
    for (int c = 0; c < NCH - 3; c++) {
        asm volatile("cp.async.wait_group 3;\n" ::);   // chunk c landed
        __syncwarp();                                  // orders consume(c-1) before refill below

        // issue chunk c+4 immediately -- decoupled from consume(c)
        if (c + 4 < NCH) {
            unsigned sb = sbase + (unsigned)islot * bufbytes;
#pragma unroll
            for (int k = 0; k < ROWV4; k++)
                cp_async16(sb + soff[k], gbase[k] + (size_t)(c + 4) * ROWV4);
            cp_commit();
        }

        // consume chunk c
        const float4* cb = smem + slot * WBUFV4 + lane * STR_V4;
#pragma unroll
        for (int j = 0; j < ROWV4; j++) {
            float4 u = cb[j];
            sir_step(S, I, u.x, u.y);
            sir_step(S, I, u.z, u.w);
        }

        slot  = (slot  == NBUF - 1) ? 0 : slot  + 1;
        islot = (islot == NBUF - 1) ? 0 : islot + 1;
    }

    // Epilogue: chunks NCH-3..NCH-1 (no further issues; decreasing wait counts)
    {
        asm volatile("cp.async.wait_group 2;\n" ::);
        __syncwarp();
        const float4* cb = smem + slot * WBUFV4 + lane * STR_V4;
#pragma unroll
        for (int j = 0; j < ROWV4; j++) {
            float4 u = cb[j];
            sir_step(S, I, u.x, u.y);
            sir_step(S, I, u.z, u.w);
        }
        slot = (slot == NBUF - 1) ? 0 : slot + 1;

        asm volatile("cp.async.wait_group 1;\n" ::);
        __syncwarp();
        const float4* cb1 = smem + slot * WBUFV4 + lane * STR_V4;
#pragma unroll
        for (int j = 0; j < ROWV4; j++) {
            float4 u = cb1[j];
            sir_step(S, I, u.x, u.y);
            sir_step(S, I, u.z, u.w);
        }
        slot = (slot == NBUF - 1) ? 0 : slot + 1;

        asm volatile("cp.async.wait_group 0;\n" ::);
        __syncwarp();
        const float4* cb0 = smem + slot * WBUFV4 + lane * STR_V4;
#pragma unroll
        for (int j = 0; j < ROWV4; j++) {
            float4 u = cb0[j];
            sir_step(S, I, u.x, u.y);
            sir_step(S, I, u.z, u.w);
        }
    }

    if (b < B) {
        float R = (total - S) - I;     // exact conservation
        for (int k = 0; k < copies; k++) {
            float* o = out + (size_t)k * (size_t)B * 3 + 3 * b;
            o[0] = S;
            o[1] = I;
            o[2] = R;
        }
    }
}

extern "C" void kernel_launch(void* const* d_in, const int* in_sizes, int n_in,
                              void* d_out, int out_size) {
    const float* in   = (const float*)d_in[0];   // inputs (B,T,F) fp32
    const float* init = (const float*)d_in[1];   // initial_state (B,3) fp32
    float* out = (float*)d_out;

    int B = in_sizes[1] / 3;
    int copies = out_size / (B * 3);
    if (copies < 1) copies = 1;

    int blocks = (B + WROWS - 1) / WROWS;        // 512 blocks of 1 warp
    sir_scan_kernel<<<blocks, BDIM>>>(in, init, out, B, copies);
}

// round 16
// speedup vs baseline: 1.0834x; 1.0834x over previous
#include <cuda_runtime.h>

// SIR scan, (B,T,F) = (16384, 2048, 2) fp32, 2048 sequential steps per row.
// R6-R15: five different cp.async schedules ALL pin at 5.2 TB/s / DRAM ~64%.
// Model: per-SM L1tex/LSU outstanding-sector cap (~17 KB/SM actually in
// flight) x loaded latency == 5.2 TB/s, schedule-invariant. R16 swaps the
// mechanism: TMA bulk copies (cp.async.bulk + mbarrier complete_tx), whose
// in-flight tracking lives in the TMA engine, not the LSU queue. Each lane
// issues one 512 B bulk copy per chunk for its own row. Consume side
// unchanged (padded smem rows, conflict-free LDS.128, 5-op SIR step,
// R recovered via exact conservation).

#define TT       2048
#define FF       2
#define CHUNK    64                     // timesteps per chunk
#define ROWV4    (CHUNK * FF / 4)       // 32 float4 per row-chunk (512 B)
#define NCH      (TT / CHUNK)           // 32 chunks
#define BDIM     32                     // 1 warp per block
#define WROWS    32                     // rows per block/warp
#define STR_V4   33                     // padded row stride in float4 (528 B)
#define BUFV4    (WROWS * STR_V4)       // 1056 float4 per buffer (16896 B)
#define NBUF     3
#define ROW_STR4 (TT * FF / 4)          // 1024 float4 per global row
#define COPY_BYTES  (ROWV4 * 16)        // 512 B per lane per chunk
#define TX_BYTES    (WROWS * COPY_BYTES)   // 16384 B per buffer fill
#define MBAR_OFF    (NBUF * BUFV4 * 16)    // mbarriers after the buffers
#define SMEM_BYTES  (MBAR_OFF + 64)

#define INV_POP 1e-6f

__device__ __forceinline__ void bulk_g2s(unsigned dst, const void* src,
                                         unsigned bytes, unsigned mbar) {
    asm volatile(
        "cp.async.bulk.shared::cluster.global.mbarrier::complete_tx::bytes "
        "[%0], [%1], %2, [%3];"
        :: "r"(dst), "l"(src), "r"(bytes), "r"(mbar) : "memory");
}

__device__ __forceinline__ void mbar_init(unsigned mbar, unsigned count) {
    asm volatile("mbarrier.init.shared.b64 [%0], %1;" :: "r"(mbar), "r"(count) : "memory");
}

__device__ __forceinline__ void mbar_expect_tx(unsigned mbar, unsigned tx) {
    asm volatile("mbarrier.arrive.expect_tx.shared.b64 _, [%0], %1;"
                 :: "r"(mbar), "r"(tx) : "memory");
}

__device__ __forceinline__ void mbar_wait(unsigned mbar, unsigned parity) {
    asm volatile(
        "{\n\t"
        ".reg .pred P;\n\t"
        "WL%=:\n\t"
        "mbarrier.try_wait.parity.acquire.cta.shared::cta.b64 P, [%0], %1, 0x989680;\n\t"
        "@P bra WD%=;\n\t"
        "bra WL%=;\n\t"
        "WD%=:\n\t"
        "}"
        :: "r"(mbar), "r"(parity) : "memory");
}

__device__ __forceinline__ void fence_async_shared() {
    asm volatile("fence.proxy.async.shared::cta;" ::: "memory");
}

// 5-op SIR step; R recovered at the end via exact conservation.
__device__ __forceinline__ void sir_step(float& S, float& I,
                                         float beta, float gamma) {
    float bp = beta * INV_POP;           // off-chain (data only)
    float a  = bp * S;                   // chain
    float d  = a - gamma;                // chain
    float Sn = __fmaf_rn(-a, I, S);      // S - new_inf
    float In = __fmaf_rn( d, I, I);      // I + (a - gamma)*I
    S = Sn;
    I = In;
}

__global__ __launch_bounds__(BDIM, 4)
void sir_scan_kernel(const float* __restrict__ in,     // (B, T, F)
                     const float* __restrict__ init,   // (B, 3)
                     float* __restrict__ out,          // copies x (B, 3)
                     int B, int copies) {
    extern __shared__ float4 smem[];   // [NBUF][BUFV4] + mbarriers

    const int lane = threadIdx.x;      // 0..31
    const int row0 = blockIdx.x * WROWS;
    int b = row0 + lane;
    if (b >= B) b = B - 1;             // B % 32 == 0 in practice; safe clamp
    const bool valid = (row0 + lane) < B;

    const float4* gin  = reinterpret_cast<const float4*>(in);
    const float4* grow = gin + (size_t)b * ROW_STR4;   // this lane's row

    float S = init[3 * b + 0];
    float I = init[3 * b + 1];
    float total = S + I + init[3 * b + 2];   // conserved quantity

    const unsigned sbase = (unsigned)__cvta_generic_to_shared(smem);
    const unsigned mbase = sbase + MBAR_OFF;
    // this lane's smem destination row inside buffer slot s:
    //   sbase + s*BUFV4*16 + lane*STR_V4*16
    const unsigned drow = sbase + (unsigned)(lane * STR_V4 * 16);
    const unsigned bufbytes = (unsigned)(BUFV4 * 16);

    if (lane == 0) {
#pragma unroll
        for (int s = 0; s < NBUF; s++) mbar_init(mbase + 8u * s, 1);
    }
    fence_async_shared();              // make mbarrier init visible to async proxy
    __syncwarp();

    // Prologue: fill all 3 buffers (chunks 0..2)
#pragma unroll
    for (int p = 0; p < NBUF; p++) {
        if (lane == 0) mbar_expect_tx(mbase + 8u * p, TX_BYTES);
        bulk_g2s(drow + (unsigned)p * bufbytes,
                 grow + (size_t)p * ROWV4, COPY_BYTES, mbase + 8u * p);
    }

    unsigned phases = 0;               // per-slot expected parity bits
    int slot = 0;
#pragma unroll 1
    for (int c = 0; c < NCH; c++) {
        const unsigned mb = mbase + 8u * slot;
        mbar_wait(mb, (phases >> slot) & 1u);
        phases ^= 1u << slot;

        // consume chunk c: own padded smem row, conflict-free LDS.128
        const float4* cb = smem + slot * BUFV4 + lane * STR_V4;
#pragma unroll
        for (int j = 0; j < ROWV4; j++) {
            float4 u = cb[j];
            sir_step(S, I, u.x, u.y);
            sir_step(S, I, u.z, u.w);
        }

        // refill this slot with chunk c+3 (each lane overwrites only the row
        // it alone just read; per-lane ordering via fence.proxy.async)
        if (c + 3 < NCH) {
            fence_async_shared();
            if (lane == 0) mbar_expect_tx(mb, TX_BYTES);
            bulk_g2s(drow + (unsigned)slot * bufbytes,
                     grow + (size_t)(c + 3) * ROWV4, COPY_BYTES, mb);
        }
        slot = (slot == NBUF - 1) ? 0 : slot + 1;
    }

    if (valid) {
        float R = (total - S) - I;     // exact conservation
        for (int k = 0; k < copies; k++) {
            float* o = out + (size_t)k * (size_t)B * 3 + 3 * b;
            o[0] = S;
            o[1] = I;
            o[2] = R;
        }
    }
}

extern "C" void kernel_launch(void* const* d_in, const int* in_sizes, int n_in,
                              void* d_out, int out_size) {
    const float* in   = (const float*)d_in[0];   // inputs (B,T,F) fp32
    const float* init = (const float*)d_in[1];   // initial_state (B,3) fp32
    float* out = (float*)d_out;

    int B = in_sizes[1] / 3;
    int copies = out_size / (B * 3);
    if (copies < 1) copies = 1;

    cudaFuncSetAttribute(sir_scan_kernel,
                         cudaFuncAttributeMaxDynamicSharedMemorySize, SMEM_BYTES);

    int blocks = (B + WROWS - 1) / WROWS;        // 512 blocks of 1 warp
    sir_scan_kernel<<<blocks, BDIM, SMEM_BYTES>>>(in, init, out, B, copies);
}